// round 1
// baseline (speedup 1.0000x reference)
#include <cuda_runtime.h>
#include <math.h>
#include <stdint.h>

#define BB 512
#define NN 50
#define DD 768
#define D4 3072
#define FLAT (NN*DD)   // 38400

// ---------------- scratch (__device__ globals; no allocation allowed) ----------------
__device__ float g_text[BB*FLAT];
__device__ float g_vis [BB*FLAT];
__device__ float g_ac  [BB*FLAT];
__device__ float s_shift[BB*FLAT];
__device__ float s_xg[(size_t)BB*NN*D4];
__device__ float s_g [BB*D4];
__device__ float s_h [BB*DD];
__device__ float s_c [BB*DD];
__device__ float s_vm[BB*DD];
__device__ float s_am[BB*DD];
__device__ float s_fc[BB*DD];
__device__ float s_W12[DD*DD];
__device__ float s_biascomb[D4];
__device__ float s_vbsum[DD];
__device__ int   s_mask[BB];

__device__ __forceinline__ float sigmoidf_(float x){ return 1.f/(1.f+expf(-x)); }

// ---------------- prep: W12 = vW1+vW2, bias combine, vb sum, zero h/c ----------------
__global__ void prep_kernel(const float* __restrict__ vW, const float* __restrict__ vb,
                            const float* __restrict__ bih, const float* __restrict__ bhh)
{
    int i = blockIdx.x*blockDim.x + threadIdx.x;
    if (i < DD*DD) s_W12[i] = vW[DD*DD + i] + vW[2*DD*DD + i];
    if (i < D4)    s_biascomb[i] = bih[i] + bhh[i];
    if (i < DD)    s_vbsum[i] = vb[i] + vb[DD+i] + vb[2*DD+i];
    if (i < BB*DD) { s_h[i] = 0.f; s_c[i] = 0.f; }
}

// ---------------- EGCE: gap over flat-[c][50] channels, k=3 conv, sigmoid gate ------
// Faithful to reshape (NOT transpose): flat index k of [n,c] row-major maps to
// channel i = k/50; source element is (n = k/768, d = k%768).
__global__ __launch_bounds__(384) void egce_kernel(
    const float* __restrict__ text, const int* __restrict__ vids,
    const int* __restrict__ aids, const float* __restrict__ vemb,
    const float* __restrict__ aemb, const float* __restrict__ w3)
{
    int b = blockIdx.x;
    int mode = blockIdx.y;     // 0=text, 1=visual(relu gather), 2=acoustic(gather)
    int tid = threadIdx.x;
    __shared__ float gap[DD];
    __shared__ float att[DD];
    __shared__ int ids[NN];
    if (tid < NN)
        ids[tid] = (mode==1) ? vids[b*NN+tid] : (mode==2 ? aids[b*NN+tid] : 0);
    __syncthreads();

    const float* src = (mode==0) ? (text + (size_t)b*FLAT) : (mode==1 ? vemb : aemb);

    auto fetch = [&](int k)->float {
        if (mode == 0) return src[k];
        int n = k / DD; int d = k - n*DD;
        float v = src[(size_t)ids[n]*DD + d];
        if (mode == 1) v = fmaxf(v, 0.f);
        return v;
    };

    for (int ch = tid; ch < DD; ch += 384) {
        float s = 0.f; int base = ch*NN;
        #pragma unroll 5
        for (int j = 0; j < NN; j++) s += fetch(base+j);
        gap[ch] = s * (1.f/NN);
    }
    __syncthreads();
    float w0 = w3[0], w1 = w3[1], w2 = w3[2];
    for (int ch = tid; ch < DD; ch += 384) {
        float a = w1*gap[ch];
        if (ch > 0)    a += w0*gap[ch-1];
        if (ch < DD-1) a += w2*gap[ch+1];
        att[ch] = 1.f/(1.f+expf(-a));
    }
    __syncthreads();
    float* out = ((mode==0) ? g_text : (mode==1 ? g_vis : g_ac)) + (size_t)b*FLAT;
    for (int k = tid; k < FLAT; k += 384)
        out[k] = fetch(k) * att[k/NN];
}

// ---------------- means over n, cosine sims, routing mask ----------------
__global__ __launch_bounds__(256) void means_cos_kernel()
{
    int b = blockIdx.x, tid = threadIdx.x;
    __shared__ float mt[DD], mv[DD], ma[DD];
    const float* pt = g_text + (size_t)b*FLAT;
    const float* pv = g_vis  + (size_t)b*FLAT;
    const float* pa = g_ac   + (size_t)b*FLAT;
    for (int d = tid; d < DD; d += 256) {
        float st=0.f, sv=0.f, sa=0.f;
        for (int n = 0; n < NN; n++) {
            st += pt[n*DD+d]; sv += pv[n*DD+d]; sa += pa[n*DD+d];
        }
        st *= (1.f/NN); sv *= (1.f/NN); sa *= (1.f/NN);
        mt[d]=st; mv[d]=sv; ma[d]=sa;
        s_vm[b*DD+d]=sv; s_am[b*DD+d]=sa;
    }
    __syncthreads();
    float p[6] = {0,0,0,0,0,0};  // tv, ta, va, tt, vv, aa
    for (int d = tid; d < DD; d += 256) {
        float t=mt[d], v=mv[d], a=ma[d];
        p[0]+=t*v; p[1]+=t*a; p[2]+=v*a; p[3]+=t*t; p[4]+=v*v; p[5]+=a*a;
    }
    __shared__ float red[256];
    __shared__ float res[6];
    for (int q = 0; q < 6; q++) {
        red[tid] = p[q]; __syncthreads();
        for (int s = 128; s > 0; s >>= 1) {
            if (tid < s) red[tid] += red[tid+s];
            __syncthreads();
        }
        if (tid == 0) res[q] = red[0];
        __syncthreads();
    }
    if (tid == 0) {
        float nt = fmaxf(sqrtf(res[3]), 1e-8f);
        float nv = fmaxf(sqrtf(res[4]), 1e-8f);
        float na = fmaxf(sqrtf(res[5]), 1e-8f);
        float rtv = res[0]/(nt*nv), rta = res[1]/(nt*na), rva = res[2]/(nv*na);
        float delta = (rtv + rta + rva) * (1.f/3.f);
        float joint = (rtv + rta + rva) * (1.f/3.f);
        int mk;
        if (rtv > delta && rta > delta && rva > delta) mk = 0;       // f_concat
        else if (joint > delta)                        mk = 1;       // f_hybrid (never)
        else                                           mk = 2;       // f_cross
        s_mask[b] = mk;
    }
}

// ---------------- generic fp32 GEMM: C[M,N] = A[M,K] @ B[N,K]^T (+epilogue) ----------
// Requires M%128==0, N%128==0, K%8==0.
// C = out_scale*(acc + (accumulate?C:0) + (bias?bias[n]:0)) + (addend?addend[m*as+n]:0)
__global__ __launch_bounds__(256) void gemm128_kernel(
    const float* __restrict__ A, const float* __restrict__ Bm, float* __restrict__ C,
    int M, int Nn, int K,
    const float* __restrict__ addend, int add_stride,
    const float* __restrict__ bias, int accumulate, float out_scale)
{
    __shared__ float As[8][128];
    __shared__ float Bs[8][128];
    int tid = threadIdx.x;
    int tx = tid & 15, ty = tid >> 4;
    const float* Ab = A  + (size_t)blockIdx.y * 128 * K;
    const float* Bb = Bm + (size_t)blockIdx.x * 128 * K;
    float acc[8][8];
    #pragma unroll
    for (int i = 0; i < 8; i++)
        #pragma unroll
        for (int j = 0; j < 8; j++) acc[i][j] = 0.f;

    int lr = tid >> 1;          // 0..127
    int lc = (tid & 1) * 4;     // 0 or 4
    for (int k0 = 0; k0 < K; k0 += 8) {
        float4 av = *reinterpret_cast<const float4*>(Ab + (size_t)lr*K + k0 + lc);
        float4 bv = *reinterpret_cast<const float4*>(Bb + (size_t)lr*K + k0 + lc);
        __syncthreads();
        As[lc+0][lr]=av.x; As[lc+1][lr]=av.y; As[lc+2][lr]=av.z; As[lc+3][lr]=av.w;
        Bs[lc+0][lr]=bv.x; Bs[lc+1][lr]=bv.y; Bs[lc+2][lr]=bv.z; Bs[lc+3][lr]=bv.w;
        __syncthreads();
        #pragma unroll
        for (int kk = 0; kk < 8; kk++) {
            float a[8], bb[8];
            #pragma unroll
            for (int i = 0; i < 8; i++) a[i]  = As[kk][ty*8+i];
            #pragma unroll
            for (int j = 0; j < 8; j++) bb[j] = Bs[kk][tx*8+j];
            #pragma unroll
            for (int i = 0; i < 8; i++)
                #pragma unroll
                for (int j = 0; j < 8; j++) acc[i][j] += a[i]*bb[j];
        }
    }
    int m0 = blockIdx.y*128 + ty*8;
    int n0 = blockIdx.x*128 + tx*8;
    for (int i = 0; i < 8; i++) {
        size_t row = (size_t)(m0+i);
        for (int j = 0; j < 8; j++) {
            int n = n0+j;
            float v = acc[i][j];
            if (accumulate) v += C[row*Nn + n];
            if (bias)       v += bias[n];
            v *= out_scale;
            if (addend)     v += addend[row*(size_t)add_stride + n];
            C[row*Nn + n] = v;
        }
    }
}

// ---------------- fusion select + residual + LayerNorm -> shift ----------------
__global__ __launch_bounds__(256) void fusion_ln_kernel(
    const float* __restrict__ cW, const float* __restrict__ cb,
    const float* __restrict__ hW, const float* __restrict__ hb,
    const float* __restrict__ ln_g, const float* __restrict__ ln_b)
{
    int bn = blockIdx.x;           // b*50 + n
    int b = bn / NN;
    int tid = threadIdx.x;
    __shared__ float buf[DD];
    __shared__ float cat[3*DD];
    __shared__ float r1[256], r2[256];
    const float* txt = g_text + (size_t)bn*DD;
    int mk = s_mask[b];
    if (mk == 2) {
        const float* fc = s_fc + (size_t)b*DD;
        for (int d = tid; d < DD; d += 256) buf[d] = fc[d] + txt[d];
    } else {
        // rare fallback: per-(b,n) projection of [text|vis|ac] by concat/hybrid W
        const float* pv = g_vis + (size_t)bn*DD;
        const float* pa = g_ac  + (size_t)bn*DD;
        for (int k = tid; k < DD; k += 256) {
            cat[k] = txt[k]; cat[DD+k] = pv[k]; cat[2*DD+k] = pa[k];
        }
        __syncthreads();
        const float* W  = (mk==0) ? cW : hW;
        const float* bv = (mk==0) ? cb : hb;
        for (int d = tid; d < DD; d += 256) {
            const float* wr = W + (size_t)d*3*DD;
            float s = bv[d];
            for (int k = 0; k < 3*DD; k++) s += cat[k]*wr[k];
            buf[d] = s + txt[d];
        }
    }
    __syncthreads();
    // two-pass LN (matches reference var = mean((x-m)^2))
    float ps = 0.f;
    for (int d = tid; d < DD; d += 256) ps += buf[d];
    r1[tid] = ps; __syncthreads();
    for (int s = 128; s > 0; s >>= 1) { if (tid < s) r1[tid] += r1[tid+s]; __syncthreads(); }
    float mean = r1[0] * (1.f/DD);
    float pq = 0.f;
    for (int d = tid; d < DD; d += 256) { float x = buf[d]-mean; pq += x*x; }
    r2[tid] = pq; __syncthreads();
    for (int s = 128; s > 0; s >>= 1) { if (tid < s) r2[tid] += r2[tid+s]; __syncthreads(); }
    float rstd = rsqrtf(r2[0]*(1.f/DD) + 1e-5f);
    float* outp = s_shift + (size_t)bn*DD;
    for (int d = tid; d < DD; d += 256)
        outp[d] = (buf[d]-mean)*rstd*ln_g[d] + ln_b[d];
}

// ---------------- LSTM elementwise gates + output residual ----------------
__global__ __launch_bounds__(512) void lstm_gates_kernel(int t, float* __restrict__ out)
{
    int idx = blockIdx.x*512 + threadIdx.x;   // < B*D
    int b = idx / DD, j = idx - b*DD;
    const float* gr = s_g + (size_t)b*D4;
    float gi = gr[j], gf = gr[DD+j], gg = gr[2*DD+j], go = gr[3*DD+j];
    float c  = s_c[idx];
    float cn = sigmoidf_(gf)*c + sigmoidf_(gi)*tanhf(gg);
    s_c[idx] = cn;
    float hn = sigmoidf_(go)*tanhf(cn);
    s_h[idx] = hn;
    size_t o = ((size_t)b*NN + t)*DD + j;
    out[o] = hn + g_text[o];
}

// ---------------- launch ----------------
extern "C" void kernel_launch(void* const* d_in, const int* in_sizes, int n_in,
                              void* d_out, int out_size)
{
    const float* text = (const float*)d_in[0];
    const int*   vids = (const int*)  d_in[1];
    const int*   aids = (const int*)  d_in[2];
    const float* vemb = (const float*)d_in[3];
    const float* aemb = (const float*)d_in[4];
    const float* w3   = (const float*)d_in[5];
    const float* Wih  = (const float*)d_in[6];
    const float* Whh  = (const float*)d_in[7];
    const float* bih  = (const float*)d_in[8];
    const float* bhh  = (const float*)d_in[9];
    const float* lng  = (const float*)d_in[10];
    const float* lnb  = (const float*)d_in[11];
    const float* cW   = (const float*)d_in[12];
    const float* cb   = (const float*)d_in[13];
    const float* hW   = (const float*)d_in[14];
    const float* hb   = (const float*)d_in[15];
    const float* vW   = (const float*)d_in[20];   // ca_vW [3,768,768]
    const float* vb   = (const float*)d_in[21];   // ca_vb [3,768]
    float* out = (float*)d_out;

    float *p_vm, *p_am, *p_fc, *p_W12, *p_vbsum, *p_shift, *p_xg, *p_bias, *p_h, *p_g;
    cudaGetSymbolAddress((void**)&p_vm, s_vm);
    cudaGetSymbolAddress((void**)&p_am, s_am);
    cudaGetSymbolAddress((void**)&p_fc, s_fc);
    cudaGetSymbolAddress((void**)&p_W12, s_W12);
    cudaGetSymbolAddress((void**)&p_vbsum, s_vbsum);
    cudaGetSymbolAddress((void**)&p_shift, s_shift);
    cudaGetSymbolAddress((void**)&p_xg, s_xg);
    cudaGetSymbolAddress((void**)&p_bias, s_biascomb);
    cudaGetSymbolAddress((void**)&p_h, s_h);
    cudaGetSymbolAddress((void**)&p_g, s_g);

    prep_kernel<<<(DD*DD + 511)/512, 512>>>(vW, vb, bih, bhh);
    egce_kernel<<<dim3(BB, 3), 384>>>(text, vids, aids, vemb, aemb, w3);
    means_cos_kernel<<<BB, 256>>>();

    // f_cross: fc = (vm@vW0^T + am@(vW1+vW2)^T + (vb0+vb1+vb2)) * (50/3)
    gemm128_kernel<<<dim3(DD/128, BB/128), 256>>>(p_vm, vW, p_fc, BB, DD, DD,
                                                  nullptr, 0, nullptr, 0, 1.f);
    gemm128_kernel<<<dim3(DD/128, BB/128), 256>>>(p_am, p_W12, p_fc, BB, DD, DD,
                                                  nullptr, 0, p_vbsum, 1, 50.f/3.f);

    fusion_ln_kernel<<<BB*NN, 256>>>(cW, cb, hW, hb, lng, lnb);

    // xg = shift @ Wih^T + (bih+bhh)   [25600, 3072]
    gemm128_kernel<<<dim3(D4/128, (BB*NN)/128), 256>>>(p_shift, Wih, p_xg,
                                                       BB*NN, D4, DD,
                                                       nullptr, 0, p_bias, 0, 1.f);
    // LSTM recurrence: 50 sequential (GEMM + gates)
    for (int t = 0; t < NN; t++) {
        gemm128_kernel<<<dim3(D4/128, BB/128), 256>>>(p_h, Whh, p_g, BB, D4, DD,
                                                      p_xg + (size_t)t*D4, NN*D4,
                                                      nullptr, 0, 1.f);
        lstm_gates_kernel<<<(BB*DD)/512, 512>>>(t, out);
    }
}

// round 3
// speedup vs baseline: 4.9419x; 4.9419x over previous
#include <cuda_runtime.h>
#include <math.h>
#include <stdint.h>

#define BB 512
#define NN 50
#define DD 768
#define D4 3072
#define FLAT (NN*DD)   // 38400

// ---------------- scratch (__device__ globals; no allocation allowed) ----------------
__device__ float g_text[BB*FLAT];
__device__ float g_vis [BB*FLAT];
__device__ float g_ac  [BB*FLAT];
__device__ float s_shift[BB*FLAT];
__device__ float s_xg[(size_t)BB*NN*D4];
__device__ float s_g [BB*D4];
__device__ float s_h [BB*DD];
__device__ float s_c [BB*DD];
__device__ float s_vm[BB*DD];
__device__ float s_am[BB*DD];
__device__ float s_fc[BB*DD];
__device__ float s_W12[DD*DD];
__device__ float s_biascomb[D4];
__device__ float s_vbsum[DD];
__device__ int   s_mask[BB];

__device__ __forceinline__ float sigmoidf_(float x){ return 1.f/(1.f+expf(-x)); }

__device__ __forceinline__ uint32_t f2tf32(float x){
    uint32_t r; asm("cvt.rna.tf32.f32 %0, %1;" : "=r"(r) : "f"(x)); return r;
}

// ---------------- prep: W12 = vW1+vW2, bias combine, vb sum, zero h/c ----------------
__global__ void prep_kernel(const float* __restrict__ vW, const float* __restrict__ vb,
                            const float* __restrict__ bih, const float* __restrict__ bhh)
{
    int i = blockIdx.x*blockDim.x + threadIdx.x;
    if (i < DD*DD) s_W12[i] = vW[DD*DD + i] + vW[2*DD*DD + i];
    if (i < D4)    s_biascomb[i] = bih[i] + bhh[i];
    if (i < DD)    s_vbsum[i] = vb[i] + vb[DD+i] + vb[2*DD+i];
    if (i < BB*DD) { s_h[i] = 0.f; s_c[i] = 0.f; }
}

// ---------------- EGCE ----------------
__global__ __launch_bounds__(384) void egce_kernel(
    const float* __restrict__ text, const int* __restrict__ vids,
    const int* __restrict__ aids, const float* __restrict__ vemb,
    const float* __restrict__ aemb, const float* __restrict__ w3)
{
    int b = blockIdx.x;
    int mode = blockIdx.y;     // 0=text, 1=visual(relu gather), 2=acoustic(gather)
    int tid = threadIdx.x;
    __shared__ float gap[DD];
    __shared__ float att[DD];
    __shared__ int ids[NN];
    if (tid < NN)
        ids[tid] = (mode==1) ? vids[b*NN+tid] : (mode==2 ? aids[b*NN+tid] : 0);
    __syncthreads();

    const float* src = (mode==0) ? (text + (size_t)b*FLAT) : (mode==1 ? vemb : aemb);

    auto fetch = [&](int k)->float {
        if (mode == 0) return src[k];
        int n = k / DD; int d = k - n*DD;
        float v = src[(size_t)ids[n]*DD + d];
        if (mode == 1) v = fmaxf(v, 0.f);
        return v;
    };

    for (int ch = tid; ch < DD; ch += 384) {
        float s = 0.f; int base = ch*NN;
        #pragma unroll 5
        for (int j = 0; j < NN; j++) s += fetch(base+j);
        gap[ch] = s * (1.f/NN);
    }
    __syncthreads();
    float w0 = w3[0], w1 = w3[1], w2 = w3[2];
    for (int ch = tid; ch < DD; ch += 384) {
        float a = w1*gap[ch];
        if (ch > 0)    a += w0*gap[ch-1];
        if (ch < DD-1) a += w2*gap[ch+1];
        att[ch] = 1.f/(1.f+expf(-a));
    }
    __syncthreads();
    float* out = ((mode==0) ? g_text : (mode==1 ? g_vis : g_ac)) + (size_t)b*FLAT;
    for (int k = tid; k < FLAT; k += 384)
        out[k] = fetch(k) * att[k/NN];
}

// ---------------- means over n, cosine sims, routing mask ----------------
__global__ __launch_bounds__(256) void means_cos_kernel()
{
    int b = blockIdx.x, tid = threadIdx.x;
    __shared__ float mt[DD], mv[DD], ma[DD];
    const float* pt = g_text + (size_t)b*FLAT;
    const float* pv = g_vis  + (size_t)b*FLAT;
    const float* pa = g_ac   + (size_t)b*FLAT;
    for (int d = tid; d < DD; d += 256) {
        float st=0.f, sv=0.f, sa=0.f;
        for (int n = 0; n < NN; n++) {
            st += pt[n*DD+d]; sv += pv[n*DD+d]; sa += pa[n*DD+d];
        }
        st *= (1.f/NN); sv *= (1.f/NN); sa *= (1.f/NN);
        mt[d]=st; mv[d]=sv; ma[d]=sa;
        s_vm[b*DD+d]=sv; s_am[b*DD+d]=sa;
    }
    __syncthreads();
    float p[6] = {0,0,0,0,0,0};  // tv, ta, va, tt, vv, aa
    for (int d = tid; d < DD; d += 256) {
        float t=mt[d], v=mv[d], a=ma[d];
        p[0]+=t*v; p[1]+=t*a; p[2]+=v*a; p[3]+=t*t; p[4]+=v*v; p[5]+=a*a;
    }
    __shared__ float red[256];
    __shared__ float res[6];
    for (int q = 0; q < 6; q++) {
        red[tid] = p[q]; __syncthreads();
        for (int s = 128; s > 0; s >>= 1) {
            if (tid < s) red[tid] += red[tid+s];
            __syncthreads();
        }
        if (tid == 0) res[q] = red[0];
        __syncthreads();
    }
    if (tid == 0) {
        float nt = fmaxf(sqrtf(res[3]), 1e-8f);
        float nv = fmaxf(sqrtf(res[4]), 1e-8f);
        float na = fmaxf(sqrtf(res[5]), 1e-8f);
        float rtv = res[0]/(nt*nv), rta = res[1]/(nt*na), rva = res[2]/(nv*na);
        float delta = (rtv + rta + rva) * (1.f/3.f);
        float joint = delta;
        int mk;
        if (rtv > delta && rta > delta && rva > delta) mk = 0;       // f_concat
        else if (joint > delta)                        mk = 1;       // f_hybrid (never)
        else                                           mk = 2;       // f_cross
        s_mask[b] = mk;
    }
}

// ---------------- tf32 tensor-core GEMM: C[M,N] = A[M,K] @ B[N,K]^T (+epilogue) ------
// Requires M%128==0, N%128==0, K%32==0.
// C = out_scale*(acc + (accumulate?C:0) + (bias?bias[n]:0)) + (addend?addend[m*as+n]:0)
__global__ __launch_bounds__(256, 1) void gemm_tf32_kernel(
    const float* __restrict__ A, const float* __restrict__ Bm, float* __restrict__ C,
    int M, int Nn, int K,
    const float* __restrict__ addend, int add_stride,
    const float* __restrict__ bias, int accumulate, float out_scale)
{
    __shared__ uint32_t As[128][36];
    __shared__ uint32_t Bs[128][36];
    int tid = threadIdx.x;
    int warp = tid >> 5, lane = tid & 31;
    int wm = (warp >> 2) * 64;          // warp tile row origin (0 or 64)
    int wn = (warp & 3) * 32;           // warp tile col origin
    int g  = lane >> 2;                 // 0..7
    int cq = lane & 3;                  // 0..3
    const float* Ab = A  + (size_t)blockIdx.y * 128 * K;
    const float* Bb = Bm + (size_t)blockIdx.x * 128 * K;

    float acc[4][4][4];
    #pragma unroll
    for (int mi = 0; mi < 4; mi++)
        #pragma unroll
        for (int ni = 0; ni < 4; ni++)
            #pragma unroll
            for (int r = 0; r < 4; r++) acc[mi][ni][r] = 0.f;

    int lrow = tid >> 3;            // 0..31
    int lcol = (tid & 7) * 4;       // 0,4,...,28
    float4 aR[4], bR[4];

    // prologue load
    #pragma unroll
    for (int p = 0; p < 4; p++) {
        aR[p] = *reinterpret_cast<const float4*>(Ab + (size_t)(p*32+lrow)*K + lcol);
        bR[p] = *reinterpret_cast<const float4*>(Bb + (size_t)(p*32+lrow)*K + lcol);
    }
    #pragma unroll
    for (int p = 0; p < 4; p++) {
        int r = p*32 + lrow;
        As[r][lcol+0]=f2tf32(aR[p].x); As[r][lcol+1]=f2tf32(aR[p].y);
        As[r][lcol+2]=f2tf32(aR[p].z); As[r][lcol+3]=f2tf32(aR[p].w);
        Bs[r][lcol+0]=f2tf32(bR[p].x); Bs[r][lcol+1]=f2tf32(bR[p].y);
        Bs[r][lcol+2]=f2tf32(bR[p].z); Bs[r][lcol+3]=f2tf32(bR[p].w);
    }
    __syncthreads();

    for (int k0 = 32; k0 <= K; k0 += 32) {
        if (k0 < K) {
            #pragma unroll
            for (int p = 0; p < 4; p++) {
                aR[p] = *reinterpret_cast<const float4*>(Ab + (size_t)(p*32+lrow)*K + k0 + lcol);
                bR[p] = *reinterpret_cast<const float4*>(Bb + (size_t)(p*32+lrow)*K + k0 + lcol);
            }
        }
        #pragma unroll
        for (int kk = 0; kk < 32; kk += 8) {
            uint32_t af[4][4], bf[4][2];
            #pragma unroll
            for (int mi = 0; mi < 4; mi++) {
                int r = wm + mi*16;
                af[mi][0] = As[r+g  ][kk+cq];
                af[mi][1] = As[r+g+8][kk+cq];
                af[mi][2] = As[r+g  ][kk+cq+4];
                af[mi][3] = As[r+g+8][kk+cq+4];
            }
            #pragma unroll
            for (int ni = 0; ni < 4; ni++) {
                int cb = wn + ni*8;
                bf[ni][0] = Bs[cb+g][kk+cq];
                bf[ni][1] = Bs[cb+g][kk+cq+4];
            }
            #pragma unroll
            for (int mi = 0; mi < 4; mi++)
                #pragma unroll
                for (int ni = 0; ni < 4; ni++) {
                    asm volatile(
                      "mma.sync.aligned.m16n8k8.row.col.f32.tf32.tf32.f32 "
                      "{%0,%1,%2,%3}, {%4,%5,%6,%7}, {%8,%9}, {%0,%1,%2,%3};"
                      : "+f"(acc[mi][ni][0]), "+f"(acc[mi][ni][1]),
                        "+f"(acc[mi][ni][2]), "+f"(acc[mi][ni][3])
                      : "r"(af[mi][0]), "r"(af[mi][1]), "r"(af[mi][2]), "r"(af[mi][3]),
                        "r"(bf[ni][0]), "r"(bf[ni][1]));
                }
        }
        __syncthreads();
        if (k0 < K) {
            #pragma unroll
            for (int p = 0; p < 4; p++) {
                int r = p*32 + lrow;
                As[r][lcol+0]=f2tf32(aR[p].x); As[r][lcol+1]=f2tf32(aR[p].y);
                As[r][lcol+2]=f2tf32(aR[p].z); As[r][lcol+3]=f2tf32(aR[p].w);
                Bs[r][lcol+0]=f2tf32(bR[p].x); Bs[r][lcol+1]=f2tf32(bR[p].y);
                Bs[r][lcol+2]=f2tf32(bR[p].z); Bs[r][lcol+3]=f2tf32(bR[p].w);
            }
            __syncthreads();
        }
    }

    // epilogue: c0:(g, 2cq), c1:(g, 2cq+1), c2:(g+8, 2cq), c3:(g+8, 2cq+1)
    int row0 = blockIdx.y*128 + wm;
    int col0 = blockIdx.x*128 + wn;
    #pragma unroll
    for (int mi = 0; mi < 4; mi++) {
        #pragma unroll
        for (int ni = 0; ni < 4; ni++) {
            #pragma unroll
            for (int r = 0; r < 4; r++) {
                int row = row0 + mi*16 + g + (r >> 1)*8;
                int n   = col0 + ni*8 + 2*cq + (r & 1);
                size_t idx = (size_t)row*Nn + n;
                float v = acc[mi][ni][r];
                if (accumulate) v += C[idx];
                if (bias)       v += bias[n];
                v *= out_scale;
                if (addend)     v += addend[(size_t)row*add_stride + n];
                C[idx] = v;
            }
        }
    }
}

// ---------------- fusion select + residual + LayerNorm -> shift ----------------
__global__ __launch_bounds__(256) void fusion_ln_kernel(
    const float* __restrict__ cW, const float* __restrict__ cb,
    const float* __restrict__ hW, const float* __restrict__ hb,
    const float* __restrict__ ln_g, const float* __restrict__ ln_b)
{
    int bn = blockIdx.x;           // b*50 + n
    int b = bn / NN;
    int tid = threadIdx.x;
    __shared__ float buf[DD];
    __shared__ float cat[3*DD];
    __shared__ float r1[256], r2[256];
    const float* txt = g_text + (size_t)bn*DD;
    int mk = s_mask[b];
    if (mk == 2) {
        const float* fc = s_fc + (size_t)b*DD;
        for (int d = tid; d < DD; d += 256) buf[d] = fc[d] + txt[d];
    } else {
        const float* pv = g_vis + (size_t)bn*DD;
        const float* pa = g_ac  + (size_t)bn*DD;
        for (int k = tid; k < DD; k += 256) {
            cat[k] = txt[k]; cat[DD+k] = pv[k]; cat[2*DD+k] = pa[k];
        }
        __syncthreads();
        const float* W  = (mk==0) ? cW : hW;
        const float* bv = (mk==0) ? cb : hb;
        for (int d = tid; d < DD; d += 256) {
            const float* wr = W + (size_t)d*3*DD;
            float s = bv[d];
            for (int k = 0; k < 3*DD; k++) s += cat[k]*wr[k];
            buf[d] = s + txt[d];
        }
    }
    __syncthreads();
    float ps = 0.f;
    for (int d = tid; d < DD; d += 256) ps += buf[d];
    r1[tid] = ps; __syncthreads();
    for (int s = 128; s > 0; s >>= 1) { if (tid < s) r1[tid] += r1[tid+s]; __syncthreads(); }
    float mean = r1[0] * (1.f/DD);
    float pq = 0.f;
    for (int d = tid; d < DD; d += 256) { float x = buf[d]-mean; pq += x*x; }
    r2[tid] = pq; __syncthreads();
    for (int s = 128; s > 0; s >>= 1) { if (tid < s) r2[tid] += r2[tid+s]; __syncthreads(); }
    float rstd = rsqrtf(r2[0]*(1.f/DD) + 1e-5f);
    float* outp = s_shift + (size_t)bn*DD;
    for (int d = tid; d < DD; d += 256)
        outp[d] = (buf[d]-mean)*rstd*ln_g[d] + ln_b[d];
}

// ---------------- LSTM elementwise gates + output residual ----------------
__global__ __launch_bounds__(512) void lstm_gates_kernel(int t, float* __restrict__ out)
{
    int idx = blockIdx.x*512 + threadIdx.x;   // < B*D
    int b = idx / DD, j = idx - b*DD;
    const float* gr = s_g + (size_t)b*D4;
    float gi = gr[j], gf = gr[DD+j], gg = gr[2*DD+j], go = gr[3*DD+j];
    float c  = s_c[idx];
    float cn = sigmoidf_(gf)*c + sigmoidf_(gi)*tanhf(gg);
    s_c[idx] = cn;
    float hn = sigmoidf_(go)*tanhf(cn);
    s_h[idx] = hn;
    size_t o = ((size_t)b*NN + t)*DD + j;
    out[o] = hn + g_text[o];
}

// ---------------- launch ----------------
extern "C" void kernel_launch(void* const* d_in, const int* in_sizes, int n_in,
                              void* d_out, int out_size)
{
    const float* text = (const float*)d_in[0];
    const int*   vids = (const int*)  d_in[1];
    const int*   aids = (const int*)  d_in[2];
    const float* vemb = (const float*)d_in[3];
    const float* aemb = (const float*)d_in[4];
    const float* w3   = (const float*)d_in[5];
    const float* Wih  = (const float*)d_in[6];
    const float* Whh  = (const float*)d_in[7];
    const float* bih  = (const float*)d_in[8];
    const float* bhh  = (const float*)d_in[9];
    const float* lng  = (const float*)d_in[10];
    const float* lnb  = (const float*)d_in[11];
    const float* cW   = (const float*)d_in[12];
    const float* cb   = (const float*)d_in[13];
    const float* hW   = (const float*)d_in[14];
    const float* hb   = (const float*)d_in[15];
    const float* vW   = (const float*)d_in[20];   // ca_vW [3,768,768]
    const float* vb   = (const float*)d_in[21];   // ca_vb [3,768]
    float* out = (float*)d_out;

    float *p_vm, *p_am, *p_fc, *p_W12, *p_vbsum, *p_shift, *p_xg, *p_bias, *p_h, *p_g;
    cudaGetSymbolAddress((void**)&p_vm, s_vm);
    cudaGetSymbolAddress((void**)&p_am, s_am);
    cudaGetSymbolAddress((void**)&p_fc, s_fc);
    cudaGetSymbolAddress((void**)&p_W12, s_W12);
    cudaGetSymbolAddress((void**)&p_vbsum, s_vbsum);
    cudaGetSymbolAddress((void**)&p_shift, s_shift);
    cudaGetSymbolAddress((void**)&p_xg, s_xg);
    cudaGetSymbolAddress((void**)&p_bias, s_biascomb);
    cudaGetSymbolAddress((void**)&p_h, s_h);
    cudaGetSymbolAddress((void**)&p_g, s_g);

    prep_kernel<<<(DD*DD + 511)/512, 512>>>(vW, vb, bih, bhh);
    egce_kernel<<<dim3(BB, 3), 384>>>(text, vids, aids, vemb, aemb, w3);
    means_cos_kernel<<<BB, 256>>>();

    // f_cross: fc = (vm@vW0^T + am@(vW1+vW2)^T + (vb0+vb1+vb2)) * (50/3)
    gemm_tf32_kernel<<<dim3(DD/128, BB/128), 256>>>(p_vm, vW, p_fc, BB, DD, DD,
                                                    nullptr, 0, nullptr, 0, 1.f);
    gemm_tf32_kernel<<<dim3(DD/128, BB/128), 256>>>(p_am, p_W12, p_fc, BB, DD, DD,
                                                    nullptr, 0, p_vbsum, 1, 50.f/3.f);

    fusion_ln_kernel<<<BB*NN, 256>>>(cW, cb, hW, hb, lng, lnb);

    // xg = shift @ Wih^T + (bih+bhh)   [25600, 3072]
    gemm_tf32_kernel<<<dim3(D4/128, (BB*NN)/128), 256>>>(p_shift, Wih, p_xg,
                                                         BB*NN, D4, DD,
                                                         nullptr, 0, p_bias, 0, 1.f);
    // LSTM recurrence: 50 sequential (GEMM + gates)
    for (int t = 0; t < NN; t++) {
        gemm_tf32_kernel<<<dim3(D4/128, BB/128), 256>>>(p_h, Whh, p_g, BB, D4, DD,
                                                        p_xg + (size_t)t*D4, NN*D4,
                                                        nullptr, 0, 1.f);
        lstm_gates_kernel<<<(BB*DD)/512, 512>>>(t, out);
    }
}